// round 17
// baseline (speedup 1.0000x reference)
#include <cuda_runtime.h>
#include <cuda_bf16.h>
#include <cstdint>
#include <math.h>

#define B_ROWS 8192
#define HID    2048
#define INP    2048
#define NCLS   10
#define POOLK  45
#define NF     45
#define ESTD   270
#define ESTP   272           // padded est row stride
#define WLD    2318   // W_lin leading dim (HID + ESTD)
#define NTILE  (HID / 128)   // 16 N-tiles
#define NTILES_TOT ((B_ROWS / 128) * NTILE)   // 1024 tiles

// ---- GEMM tiling: bf16 m16n8k16, tile 128x128, 4 warps, warp tile 64x64 ----
#define BM 128
#define BN 128
#define BKS 64               // K (bf16 elems) per stage
#define NSTG_IT (INP / BKS)  // 32 stage iterations
#define LDKB 72              // padded bf16 per smem row (144 B)
#define SA_BYTES (BM * LDKB * 2)       // 18432
#define STAGE_BYTES (2 * SA_BYTES)     // 36864 (A + B)
#define NTHREADS 128          // 4 warps: 2M x 2N, warp tile 64x64
#define GRID_PERSIST 444      // 148 SMs x 3 CTAs

// epilogue smem overlay (floats, at buffer-1 start)
// STG_STRIDE must be >= 128 (row span) — 124 in R16 made columns overlap (bug)
#define STG_STRIDE 132
#define SWL_OFF (64 * STG_STRIDE)              // 8448
#define EPI_BYTES ((SWL_OFF + NCLS * 128) * 4) // 38912
#define GEMM_SMEM_BYTES (STAGE_BYTES + EPI_BYTES)  // 75776 -> 3 CTAs/SM (227328 B)

// Scratch (device globals — no runtime allocation)
__device__ __nv_bfloat16 g_xb[(size_t)B_ROWS * INP];
__device__ __nv_bfloat16 g_wb[(size_t)HID * INP];
__device__ float  g_Wl[NCLS * HID];
__device__ float  g_WlE[NCLS * 288];
__device__ float  g_lg_part[(size_t)B_ROWS * NTILE * NCLS];   // [row][tile*10]
__device__ float  g_pool_part[(size_t)NF * 2 * B_ROWS];
__device__ float  g_est[(size_t)B_ROWS * ESTP];               // [row][272]
__device__ unsigned g_tile_ctr;

// ------------------------------------------------------------------
__device__ __forceinline__ uint32_t smem_u32(const void* p) {
    return (uint32_t)__cvta_generic_to_shared(p);
}
__device__ __forceinline__ void cp16(uint32_t dst, const void* src) {
    asm volatile("cp.async.cg.shared.global [%0], [%1], 16;\n" :: "r"(dst), "l"(src));
}
__device__ __forceinline__ void ldsm_x4(uint32_t& r0, uint32_t& r1, uint32_t& r2,
                                        uint32_t& r3, uint32_t addr) {
    asm volatile("ldmatrix.sync.aligned.m8n8.x4.shared.b16 {%0,%1,%2,%3}, [%4];"
                 : "=r"(r0), "=r"(r1), "=r"(r2), "=r"(r3) : "r"(addr));
}
__device__ __forceinline__ void mma_bf16(float* d, const uint32_t* a,
                                         uint32_t b0, uint32_t b1) {
    asm volatile(
        "mma.sync.aligned.m16n8k16.row.col.f32.bf16.bf16.f32 "
        "{%0,%1,%2,%3}, {%4,%5,%6,%7}, {%8,%9}, {%0,%1,%2,%3};"
        : "+f"(d[0]), "+f"(d[1]), "+f"(d[2]), "+f"(d[3])
        : "r"(a[0]), "r"(a[1]), "r"(a[2]), "r"(a[3]), "r"(b0), "r"(b1));
}
__device__ __forceinline__ float tanh_fast(float x) {
    float r;
    asm("tanh.approx.f32 %0, %1;" : "=f"(r) : "f"(x));
    return r;
}

// ------------------------------------------------------------------
// Kernel 0a/0b: fp32 -> bf16 (round-to-nearest)
// ------------------------------------------------------------------
__global__ __launch_bounds__(256) void cvt_bf16_kernel(
    const float* __restrict__ src, __nv_bfloat16* __restrict__ dst, int n4)
{
    int i = blockIdx.x * 256 + threadIdx.x;
    if (i >= n4) return;
    float4 v = ((const float4*)src)[i];
    __nv_bfloat162* d2 = (__nv_bfloat162*)dst;
    d2[2 * i]     = __floats2bfloat162_rn(v.x, v.y);
    d2[2 * i + 1] = __floats2bfloat162_rn(v.z, v.w);
}

// ------------------------------------------------------------------
// Kernel 0c: W_lin pack + tile counter reset
// ------------------------------------------------------------------
#define PREP_N (NCLS * HID + NCLS * ESTD)
__global__ __launch_bounds__(256) void prep_wl_kernel(const float* __restrict__ Wl)
{
    int idx = blockIdx.x * 256 + threadIdx.x;
    if (idx == 0) g_tile_ctr = 0;
    if (idx >= PREP_N) return;
    int n1 = NCLS * HID;
    if (idx < n1) {
        int c = idx / HID, k = idx % HID;
        g_Wl[idx] = Wl[(size_t)c * WLD + k];
    } else {
        int j = idx - n1;
        int c = j / ESTD, e = j % ESTD;
        g_WlE[c * 288 + e] = Wl[(size_t)c * WLD + HID + e];
    }
}

// ------------------------------------------------------------------
// Kernel 1: PERSISTENT GEMM(bf16) + tanh + fused pool/logits partials
// 444 CTAs, atomic work-stealing, cross-tile prologue overlap
// ------------------------------------------------------------------
__device__ __forceinline__ void load_stage(char* sbase, int bm, int bn, int kt, int tid)
{
    uint32_t su = smem_u32(sbase);
    #pragma unroll
    for (int i = 0; i < 8; i++) {
        int ci = tid + i * NTHREADS;
        int r = ci >> 3, ko = (ci & 7) << 3;
        cp16(su + (uint32_t)(r * LDKB + ko) * 2,
             g_xb + (size_t)(bm + r) * INP + kt + ko);
    }
    uint32_t sub = su + SA_BYTES;
    #pragma unroll
    for (int i = 0; i < 8; i++) {
        int ci = tid + i * NTHREADS;
        int r = ci >> 3, ko = (ci & 7) << 3;
        cp16(sub + (uint32_t)(r * LDKB + ko) * 2,
             g_wb + (size_t)(bn + r) * INP + kt + ko);
    }
    asm volatile("cp.async.commit_group;" ::: "memory");
}

__global__ __launch_bounds__(NTHREADS, 3) void gemm_tanh_kernel(
    const float* __restrict__ b_ih, const float* __restrict__ b_hh)
{
    extern __shared__ char dsmc[];
    __shared__ float sbias[BN];
    __shared__ unsigned s_tile;

    const int tid  = threadIdx.x;
    const int warp = tid >> 5;
    const int lane = tid & 31;
    const int qid  = lane >> 2;
    const int tq   = lane & 3;

    const int wm = (warp & 1) * 64;
    const int wn = (warp >> 1) * 64;

    const uint32_t aoff = (uint32_t)((lane & 15) * LDKB + (lane >> 4) * 8) * 2;
    const uint32_t boff = (uint32_t)((wn + ((lane >> 4) & 1) * 8 + (lane & 7)) * LDKB) * 2
                        + ((lane >> 3) & 1) * 16;

    // first tile
    if (tid == 0) s_tile = atomicAdd(&g_tile_ctr, 1u);
    __syncthreads();
    unsigned t = s_tile;
    if (t >= NTILES_TOT) return;
    int bm = (int)(t >> 4) * BM;
    int bn = (int)(t & 15) * BN;

    sbias[tid] = b_ih[bn + tid] + b_hh[bn + tid];
    load_stage(dsmc,               bm, bn, 0,   tid);
    load_stage(dsmc + STAGE_BYTES, bm, bn, BKS, tid);

    while (true) {
        float acc[4][8][4];
        #pragma unroll
        for (int mf = 0; mf < 4; mf++)
            #pragma unroll
            for (int nf = 0; nf < 8; nf++)
                #pragma unroll
                for (int e = 0; e < 4; e++) acc[mf][nf][e] = 0.f;

        for (int s = 0; s < NSTG_IT; s++) {
            if (s >= NSTG_IT - 1)
                asm volatile("cp.async.wait_group 0;" ::: "memory");
            else
                asm volatile("cp.async.wait_group 1;" ::: "memory");
            __syncthreads();

            char* sA = dsmc + (s & 1) * STAGE_BYTES;
            uint32_t sAu = smem_u32(sA);
            uint32_t sBu = sAu + SA_BYTES;

            #pragma unroll
            for (int kk = 0; kk < BKS; kk += 16) {
                uint32_t b[8][2];
                #pragma unroll
                for (int p = 0; p < 4; p++) {
                    uint32_t addr = sBu + boff + (uint32_t)(p * 16 * LDKB * 2) + kk * 2;
                    ldsm_x4(b[2 * p][0], b[2 * p][1], b[2 * p + 1][0], b[2 * p + 1][1], addr);
                }
                #pragma unroll
                for (int mf = 0; mf < 4; mf++) {
                    uint32_t a[4];
                    uint32_t addr = sAu + aoff +
                        (uint32_t)((wm + mf * 16) * LDKB + kk) * 2;
                    ldsm_x4(a[0], a[1], a[2], a[3], addr);
                    #pragma unroll
                    for (int nf = 0; nf < 8; nf++)
                        mma_bf16(acc[mf][nf], a, b[nf][0], b[nf][1]);
                }
            }

            if (s + 2 < NSTG_IT) {
                __syncthreads();
                load_stage(dsmc + (s & 1) * STAGE_BYTES, bm, bn, (s + 2) * BKS, tid);
            }
        }

        // ---- grab next tile, start its stage-0 load before the epilogue ----
        __syncthreads();
        if (tid == 0) s_tile = atomicAdd(&g_tile_ctr, 1u);
        __syncthreads();
        unsigned t2 = s_tile;
        bool valid = t2 < NTILES_TOT;
        int bm2 = (int)(t2 >> 4) * BM;
        int bn2 = (int)(t2 & 15) * BN;
        if (valid) load_stage(dsmc, bm2, bn2, 0, tid);   // -> buffer 0

        // ---------- fused epilogue in buffer 1 (STG_STRIDE=132, no overlap) ----------
        float* stg = (float*)(dsmc + STAGE_BYTES);
        float* sWl = stg + SWL_OFF;

        for (int i = tid; i < NCLS * 128; i += NTHREADS)
            sWl[i] = g_Wl[(i >> 7) * HID + bn + (i & 127)];

        const int r = tid;
        const int tileN = bn >> 7;
        int f0 = bn / POOLK;
        int f1 = (bn + 127) / POOLK; if (f1 > NF - 1) f1 = NF - 1;

        float lg[NCLS];
        #pragma unroll
        for (int c = 0; c < NCLS; c++) lg[c] = 0.f;
        float fsum[4] = {0.f, 0.f, 0.f, 0.f};

        for (int pass = 0; pass < 2; pass++) {
            __syncthreads();
            if ((warp >> 1) == pass) {
                #pragma unroll
                for (int mf = 0; mf < 4; mf++) {
                    int r0 = wm + mf * 16 + qid;
                    #pragma unroll
                    for (int nf = 0; nf < 8; nf++) {
                        int lc = nf * 8 + tq * 2;
                        int gc = wn + lc;
                        float b0 = sbias[gc], b1 = sbias[gc + 1];
                        stg[lc * STG_STRIDE + r0]           = tanh_fast(acc[mf][nf][0] + b0);
                        stg[(lc + 1) * STG_STRIDE + r0]     = tanh_fast(acc[mf][nf][1] + b1);
                        stg[lc * STG_STRIDE + r0 + 8]       = tanh_fast(acc[mf][nf][2] + b0);
                        stg[(lc + 1) * STG_STRIDE + r0 + 8] = tanh_fast(acc[mf][nf][3] + b1);
                    }
                }
            }
            __syncthreads();

            const int cbase = pass * 64;
            #pragma unroll 4
            for (int j = 0; j < 64; j++) {
                float y = stg[j * STG_STRIDE + r];
                #pragma unroll
                for (int c = 0; c < NCLS; c++) lg[c] += y * sWl[c * 128 + cbase + j];
            }
            for (int fi = 0; fi <= f1 - f0; fi++) {
                int f = f0 + fi;
                int c0 = POOLK * f - bn, c1 = c0 + POOLK - 1;
                if (c0 < cbase) c0 = cbase;
                if (c1 > cbase + 63) c1 = cbase + 63;
                float sum = 0.f;
                for (int c = c0; c <= c1; c++) sum += stg[(c - cbase) * STG_STRIDE + r];
                fsum[fi] += sum;
            }
        }

        float* dst = &g_lg_part[((size_t)(bm + r) * NTILE + tileN) * NCLS];
        #pragma unroll
        for (int c = 0; c < NCLS; c++) dst[c] = lg[c];
        for (int fi = 0; fi <= f1 - f0; fi++) {
            int f = f0 + fi;
            int c0 = POOLK * f - bn;
            int c1 = c0 + POOLK - 1;
            if (c0 < 0 || c1 > 127) {
                int slot = (tileN == (POOLK * f) >> 7) ? 0 : 1;
                g_pool_part[((size_t)f * 2 + slot) * B_ROWS + bm + r] = fsum[fi];
            } else {
                g_pool_part[((size_t)f * 2 + 0) * B_ROWS + bm + r] = fsum[fi];
            }
        }

        __syncthreads();   // stg + sbias reads done
        if (!valid) break;
        bm = bm2; bn = bn2;
        sbias[tid] = b_ih[bn + tid] + b_hh[bn + tid];
        load_stage(dsmc + STAGE_BYTES, bm, bn, BKS, tid);   // stage-1 -> buffer 1
    }
}

// ------------------------------------------------------------------
// Kernel 2: per-feature scan of (v, v^2) + DIRECT est emission
// 1024 threads, smem history ring gives cs[i-L] for L in {32,128,512}
// ------------------------------------------------------------------
#define SCT 1024
__global__ __launch_bounds__(SCT) void scan_kernel()
{
    const int f = blockIdx.x;
    const int t = threadIdx.x, lane = t & 31, w = t >> 5;
    const bool two = ((POOLK * f) >> 7) != ((POOLK * f + POOLK - 1) >> 7);
    const float* P0 = &g_pool_part[(size_t)f * 2 * B_ROWS];
    const float* P1 = P0 + B_ROWS;
    __shared__ float2 wtot[32];
    __shared__ float2 hist[1536];   // [0..511] prev tail, [512..1535] current
    float2 carry = make_float2(0.f, 0.f);

    for (int chunk = 0; chunk < B_ROWS / SCT; chunk++) {
        int i = chunk * SCT + t;
        float v = P0[i];
        if (two) v += P1[i];
        v *= (1.0f / (float)POOLK);
        float2 s = make_float2(v, v * v);
        #pragma unroll
        for (int off = 1; off < 32; off <<= 1) {
            float a  = __shfl_up_sync(0xffffffffu, s.x, off);
            float b2 = __shfl_up_sync(0xffffffffu, s.y, off);
            if (lane >= off) { s.x += a; s.y += b2; }
        }
        if (lane == 31) wtot[w] = s;
        __syncthreads();
        if (w == 0) {
            float2 xx = wtot[lane];
            #pragma unroll
            for (int off = 1; off < 32; off <<= 1) {
                float a  = __shfl_up_sync(0xffffffffu, xx.x, off);
                float b2 = __shfl_up_sync(0xffffffffu, xx.y, off);
                if (lane >= off) { xx.x += a; xx.y += b2; }
            }
            wtot[lane] = xx;
        }
        __syncthreads();
        float2 pre = carry;
        if (w > 0) { pre.x += wtot[w - 1].x; pre.y += wtot[w - 1].y; }
        float2 cs = make_float2(s.x + pre.x, s.y + pre.y);
        hist[512 + t] = cs;
        carry.x += wtot[31].x;
        carry.y += wtot[31].y;
        __syncthreads();

        // est emission for row i, feature f, windows {32,128,512}
        float* erow = &g_est[(size_t)i * ESTP + f * 6];
        #pragma unroll
        for (int j = 0; j < 3; j++) {
            const int L = (j == 0) ? 32 : (j == 1) ? 128 : 512;
            float2 c0 = make_float2(0.f, 0.f);
            if (i >= L) c0 = hist[512 + t - L];
            float cnt = fminf((float)(i + 1), (float)L);
            float inv = 1.0f / cnt;
            float m = (cs.x - c0.x) * inv;
            erow[j * 2]     = m;
            erow[j * 2 + 1] = (cs.y - c0.y) * inv - m * m;
        }
        __syncthreads();
        if (t < 512) hist[t] = hist[1024 + t];   // keep last 512 as history
        __syncthreads();
    }
}

// ------------------------------------------------------------------
// Kernel 3: final — warp per row: tile partials + est GEMV + softmax
// ------------------------------------------------------------------
__global__ __launch_bounds__(256) void final_kernel(
    const float* __restrict__ b_lin, float* __restrict__ out)
{
    const int t = threadIdx.x, lane = t & 31, wid = t >> 5;
    const int row = blockIdx.x * 8 + wid;

    float acc[NCLS];
    #pragma unroll
    for (int c = 0; c < NCLS; c++) acc[c] = 0.f;

    if (lane < NTILE) {
        const float* p = &g_lg_part[((size_t)row * NTILE + lane) * NCLS];
        #pragma unroll
        for (int c = 0; c < NCLS; c++) acc[c] += p[c];
    }
    const float* erow = &g_est[(size_t)row * ESTP];
    for (int e = lane; e < ESTD; e += 32) {
        float ev = erow[e];
        #pragma unroll
        for (int c = 0; c < NCLS; c++) acc[c] += ev * g_WlE[c * 288 + e];
    }
    #pragma unroll
    for (int c = 0; c < NCLS; c++) {
        #pragma unroll
        for (int off = 16; off > 0; off >>= 1)
            acc[c] += __shfl_down_sync(0xffffffffu, acc[c], off);
    }
    if (lane == 0) {
        float lg[NCLS], mx = -1e30f;
        #pragma unroll
        for (int c = 0; c < NCLS; c++) { lg[c] = acc[c] + b_lin[c]; mx = fmaxf(mx, lg[c]); }
        float sum = 0.f;
        #pragma unroll
        for (int c = 0; c < NCLS; c++) { lg[c] = expf(lg[c] - mx); sum += lg[c]; }
        float inv = 1.0f / sum;
        #pragma unroll
        for (int c = 0; c < NCLS; c++) out[row * NCLS + c] = lg[c] * inv;
    }
}

// ------------------------------------------------------------------
extern "C" void kernel_launch(void* const* d_in, const int* in_sizes, int n_in,
                              void* d_out, int out_size)
{
    (void)in_sizes; (void)n_in; (void)out_size;
    const float* x     = (const float*)d_in[0];
    const float* W_ih  = (const float*)d_in[1];
    // d_in[2] = W_hh — dead: seq_len==1 and h0==0
    const float* b_ih  = (const float*)d_in[3];
    const float* b_hh  = (const float*)d_in[4];
    const float* W_lin = (const float*)d_in[5];
    const float* b_lin = (const float*)d_in[6];
    float* out = (float*)d_out;

    cudaFuncSetAttribute(gemm_tanh_kernel,
                         cudaFuncAttributeMaxDynamicSharedMemorySize, GEMM_SMEM_BYTES);

    __nv_bfloat16 *xb, *wb;
    cudaGetSymbolAddress((void**)&xb, g_xb);
    cudaGetSymbolAddress((void**)&wb, g_wb);

    int nx4 = (B_ROWS * INP) / 4;
    int nw4 = (HID * INP) / 4;

    // 3 prep launches so the GEMM sits in the ncu capture slot (#4)
    cvt_bf16_kernel<<<(nx4 + 255) / 256, 256>>>(x, xb, nx4);
    cvt_bf16_kernel<<<(nw4 + 255) / 256, 256>>>(W_ih, wb, nw4);
    prep_wl_kernel<<<(PREP_N + 255) / 256, 256>>>(W_lin);

    gemm_tanh_kernel<<<GRID_PERSIST, NTHREADS, GEMM_SMEM_BYTES>>>(b_ih, b_hh);
    scan_kernel<<<NF, SCT>>>();
    final_kernel<<<B_ROWS / 8, 256>>>(b_lin, out);
}